// round 14
// baseline (speedup 1.0000x reference)
#include <cuda_runtime.h>
#include <cstdint>
#include <math.h>

// Problem constants
#define N_ROWS 16384
#define DHALF  256
#define KDIM   512                     // s8 bytes per row = floats per row
#define VCODES 8192

// Tiling: full-K stages, A resident, 16 warps in 4x4, warp tile 32x32
#define BR 128
#define BC 128
#define N_TILES (VCODES / BC)          // 64 stages
#define NTHREADS 512

#define MARGIN 0.5f
#define CAP 48

// SMEM: rows padded to 528B (528 mod 128 = 16 -> conflict-free ldmatrix)
#define ROWB 528
#define A_STAGE (BR * ROWB)            // 67584
#define B_STAGE (BC * ROWB)            // 67584
#define OFF_A  0
#define OFF_B0 (A_STAGE)
#define OFF_B1 (A_STAGE + B_STAGE)
#define OFF_CAND (A_STAGE + 2 * B_STAGE)          // 202752: uint16[128][2][CAP]
#define OFF_CNT  (OFF_CAND + BR * 2 * CAP * 2)    // 227328: int[128][2]
#define SMEM_TOTAL (OFF_CNT + 1024)               // 228352

// Scratch globals
__device__ float   g_w2[VCODES];
__device__ int     g_counts[VCODES];
__device__ int     g_idx[N_ROWS];
__device__ float   g_bmax[384];        // per-block maxima: [0..255]=z, [256..383]=w
__device__ float   g_maxz;
__device__ float   g_maxw;
__device__ int8_t  g_z8[(size_t)N_ROWS * KDIM];
__device__ int8_t  g_w8[(size_t)VCODES * KDIM];

// ---------------------------------------------------------------------------
__device__ __forceinline__ uint32_t smem_u32(const void* p) {
    uint32_t a;
    asm("{ .reg .u64 t; cvta.to.shared.u64 t, %1; cvt.u32.u64 %0, t; }" : "=r"(a) : "l"(p));
    return a;
}
#define CP_ASYNC16(dst, src) \
    asm volatile("cp.async.cg.shared.global [%0], [%1], 16;" :: "r"(dst), "l"(src) : "memory")
#define CP_ASYNC_COMMIT() asm volatile("cp.async.commit_group;" ::: "memory")
#define CP_ASYNC_WAIT0()  asm volatile("cp.async.wait_group 0;" ::: "memory")

#define LDSM_X4(r0, r1, r2, r3, addr) \
    asm volatile("ldmatrix.sync.aligned.m8n8.x4.shared.b16 {%0,%1,%2,%3}, [%4];" \
        : "=r"(r0), "=r"(r1), "=r"(r2), "=r"(r3) : "r"(addr))

#define MMA_S8(C, a0, a1, a2, a3, b0, b1) \
    asm volatile("mma.sync.aligned.m16n8k32.row.col.s32.s8.s8.s32 " \
        "{%0,%1,%2,%3}, {%4,%5,%6,%7}, {%8,%9}, {%0,%1,%2,%3};" \
        : "+r"((C)[0]), "+r"((C)[1]), "+r"((C)[2]), "+r"((C)[3]) \
        : "r"(a0), "r"(a1), "r"(a2), "r"(a3), "r"(b0), "r"(b1))

// ---------------------------------------------------------------------------
// Pass 1 of max-abs: per-block maxima (no atomics). Also zeroes g_counts.
// Grid: 384 blocks x 256. seg 0: zr, seg 1: zi, seg 2: w.
// ---------------------------------------------------------------------------
__global__ void maxabs3_kernel(const float* __restrict__ zr, const float* __restrict__ zi,
                               const float* __restrict__ w) {
    __shared__ float sred[8];
    int seg = blockIdx.x >> 7;
    int b   = blockIdx.x & 127;
    const float* p = (seg == 0) ? zr : (seg == 1) ? zi : w;
    int n4 = (seg == 2) ? (VCODES * KDIM / 4) : (N_ROWS * DHALF / 4);
    int stride = 128 * blockDim.x;
    float m = 0.f;
    for (int i = b * blockDim.x + threadIdx.x; i < n4; i += stride) {
        float4 v = ((const float4*)p)[i];
        m = fmaxf(m, fmaxf(fmaxf(fabsf(v.x), fabsf(v.y)), fmaxf(fabsf(v.z), fabsf(v.w))));
    }
#pragma unroll
    for (int s = 16; s >= 1; s >>= 1) m = fmaxf(m, __shfl_xor_sync(0xffffffffu, m, s));
    if ((threadIdx.x & 31) == 0) sred[threadIdx.x >> 5] = m;
    __syncthreads();
    if (threadIdx.x == 0) {
        float bm = sred[0];
#pragma unroll
        for (int i = 1; i < 8; i++) bm = fmaxf(bm, sred[i]);
        g_bmax[blockIdx.x] = bm;
    }
    int gi = blockIdx.x * blockDim.x + threadIdx.x;
    if (gi < VCODES) g_counts[gi] = 0;
}

// block-reduce helper over g_bmax[base .. base+n)
__device__ __forceinline__ float reduce_bmax(float* sm, int base, int n) {
    int t = threadIdx.x;
    sm[t] = (t < n) ? g_bmax[base + t] : 0.f;
    __syncthreads();
    for (int s = 128; s >= 1; s >>= 1) {
        if (t < s) sm[t] = fmaxf(sm[t], sm[t + s]);
        __syncthreads();
    }
    float r = sm[0];
    __syncthreads();
    return r;
}

// ---------------------------------------------------------------------------
__global__ void quant_z_kernel(const float* __restrict__ zr, const float* __restrict__ zi) {
    __shared__ float sm[256];
    float mz = reduce_bmax(sm, 0, 256);
    if (blockIdx.x == 0 && threadIdx.x == 0) g_maxz = mz;
    float inv = 127.f / mz;
    int q = blockIdx.x * blockDim.x + threadIdx.x;           // float4 index
    if (q >= N_ROWS * KDIM / 4) return;
    int row = q >> 7, kq = (q & 127) * 4;
    float4 v = (kq < DHALF) ? *(const float4*)&zr[(size_t)row * DHALF + kq]
                            : *(const float4*)&zi[(size_t)row * DHALF + kq - DHALF];
    char4 c;
    c.x = (char)__float2int_rn(v.x * inv);
    c.y = (char)__float2int_rn(v.y * inv);
    c.z = (char)__float2int_rn(v.z * inv);
    c.w = (char)__float2int_rn(v.w * inv);
    *(char4*)&g_z8[(size_t)row * KDIM + kq] = c;
}

// fused: quantize w + compute w2 in one pass (one warp per code row)
__global__ void quant_w2_kernel(const float* __restrict__ w) {
    __shared__ float sm[256];
    float mw = reduce_bmax(sm, 256, 128);
    if (blockIdx.x == 0 && threadIdx.x == 0) g_maxw = mw;
    float inv = 127.f / mw;
    int row  = blockIdx.x * 8 + (threadIdx.x >> 5);
    int lane = threadIdx.x & 31;
    const float4* wr = (const float4*)(w + (size_t)row * KDIM);
    float ss = 0.f;
#pragma unroll
    for (int p = 0; p < 4; p++) {
        float4 v = wr[lane + p * 32];
        ss = fmaf(v.x, v.x, ss); ss = fmaf(v.y, v.y, ss);
        ss = fmaf(v.z, v.z, ss); ss = fmaf(v.w, v.w, ss);
        char4 c;
        c.x = (char)__float2int_rn(v.x * inv);
        c.y = (char)__float2int_rn(v.y * inv);
        c.z = (char)__float2int_rn(v.z * inv);
        c.w = (char)__float2int_rn(v.w * inv);
        *(char4*)&g_w8[(size_t)row * KDIM + (lane + p * 32) * 4] = c;
    }
#pragma unroll
    for (int m = 16; m >= 1; m >>= 1) ss += __shfl_xor_sync(0xffffffffu, ss, m);
    if (lane == 0) g_w2[row] = ss;
}

// ---------------------------------------------------------------------------
// Loaders: full 128-row x 512B tiles, 512 threads (8 chunks per thread)
// ---------------------------------------------------------------------------
__device__ __forceinline__ void load_A(uint32_t sa, int r0, int t) {
#pragma unroll
    for (int p = 0; p < 8; p++) {
        int e = t + p * NTHREADS;
        int row = e >> 5, g = e & 31;
        CP_ASYNC16(sa + (uint32_t)(row * ROWB + g * 16),
                   &g_z8[(size_t)(r0 + row) * KDIM + g * 16]);
    }
}
__device__ __forceinline__ void load_B(uint32_t sbb, int ct, int t) {
#pragma unroll
    for (int p = 0; p < 8; p++) {
        int e = t + p * NTHREADS;
        int row = e >> 5, g = e & 31;
        CP_ASYNC16(sbb + (uint32_t)(row * ROWB + g * 16),
                   &g_w8[(size_t)(ct * BC + row) * KDIM + g * 16]);
    }
}

// ---------------------------------------------------------------------------
// Fused: s8 IMMA prune -> candidate lists -> exact fp32 rescore
// 16 warps: warp_m = wid&3 (32 rows), warp_n = wid>>2 (32 cols). 4 warps/SMSP.
// ---------------------------------------------------------------------------
__global__ __launch_bounds__(NTHREADS, 1)
void vq_mma_kernel(const float* __restrict__ zr, const float* __restrict__ zi,
                   const float* __restrict__ w) {
    extern __shared__ char smem[];
    const uint32_t sb = smem_u32(smem);
    const int t = threadIdx.x;
    const int wid = t >> 5, lane = t & 31;
    const int warp_m = wid & 3, warp_n = wid >> 2;
    const int q = lane >> 2, c4 = lane & 3;
    const int r0 = blockIdx.x * BR;

    const float s2 = -2.f * (g_maxz / 127.f) * (g_maxw / 127.f);

    uint16_t* cand = (uint16_t*)(smem + OFF_CAND);
    int*      cnt  = (int*)(smem + OFF_CNT);
    if (t < 256) cnt[t] = 0;                      // 256 counters [128][2]

    int acc[2][4][4];                             // [mt][nt8][frag] = 32 regs
#pragma unroll
    for (int mt = 0; mt < 2; mt++)
#pragma unroll
        for (int nt = 0; nt < 4; nt++)
#pragma unroll
            for (int j = 0; j < 4; j++) acc[mt][nt][j] = 0;
    float run[4] = {3.4e38f, 3.4e38f, 3.4e38f, 3.4e38f};

    load_A(sb + OFF_A, r0, t);
    load_B(sb + OFF_B0, 0, t);
    CP_ASYNC_COMMIT();

    const uint32_t a_row  = (lane & 7) + ((lane >> 3) & 1) * 8;
    const uint32_t a_koff = ((lane >> 4) & 1) * 16;
    const uint32_t b_row  = (lane & 7) + ((lane >> 4) & 1) * 8;
    const uint32_t b_koff = ((lane >> 3) & 1) * 16;

    const uint32_t a_base = sb + OFF_A + (warp_m * 32 + a_row) * ROWB + a_koff;
    const int lidx_base = warp_n >> 1;            // two warp_n share a list

    for (int ct = 0; ct < N_TILES; ct++) {
        CP_ASYNC_WAIT0();
        __syncthreads();
        if (ct + 1 < N_TILES) {
            load_B(sb + (((ct + 1) & 1) ? OFF_B1 : OFF_B0), ct + 1, t);
            CP_ASYNC_COMMIT();
        }

        {
            const uint32_t bbase = sb + ((ct & 1) ? OFF_B1 : OFF_B0)
                                 + (warp_n * 32 + b_row) * ROWB + b_koff;
#pragma unroll
            for (int kb = 0; kb < 16; kb++) {
                const uint32_t koff = kb * 32;
                uint32_t a[2][4];
#pragma unroll
                for (int mt = 0; mt < 2; mt++)
                    LDSM_X4(a[mt][0], a[mt][1], a[mt][2], a[mt][3],
                            a_base + mt * (16 * ROWB) + koff);
#pragma unroll
                for (int ntp = 0; ntp < 2; ntp++) {
                    uint32_t b0, b1, b2, b3;
                    LDSM_X4(b0, b1, b2, b3, bbase + ntp * (16 * ROWB) + koff);
#pragma unroll
                    for (int mt = 0; mt < 2; mt++) {
                        MMA_S8(acc[mt][2 * ntp],     a[mt][0], a[mt][1], a[mt][2], a[mt][3], b0, b1);
                        MMA_S8(acc[mt][2 * ntp + 1], a[mt][0], a[mt][1], a[mt][2], a[mt][3], b2, b3);
                    }
                }
            }
        }

        // ---- stage = full K: scores, running min, candidate append ----
        {
            const int c0t = ct * BC;
            float w2v[4][2];
#pragma unroll
            for (int nt = 0; nt < 4; nt++) {
                int c = c0t + warp_n * 32 + nt * 8 + 2 * c4;
                w2v[nt][0] = __ldg(&g_w2[c]);
                w2v[nt][1] = __ldg(&g_w2[c + 1]);
            }
#pragma unroll
            for (int rr = 0; rr < 4; rr++) {
                const int mt = rr >> 1, h = rr & 1;
                float s[8];
#pragma unroll
                for (int nt = 0; nt < 4; nt++) {
                    s[2 * nt]     = fmaf(s2, (float)acc[mt][nt][2 * h],     w2v[nt][0]);
                    s[2 * nt + 1] = fmaf(s2, (float)acc[mt][nt][2 * h + 1], w2v[nt][1]);
                }
                float m = s[0];
#pragma unroll
                for (int j = 1; j < 8; j++) m = fminf(m, s[j]);
                m = fminf(m, __shfl_xor_sync(0xffffffffu, m, 1));
                m = fminf(m, __shfl_xor_sync(0xffffffffu, m, 2));
                run[rr] = fminf(run[rr], m);
                const float thr = run[rr] + MARGIN;
                const int rowl = warp_m * 32 + mt * 16 + h * 8 + q;
                const int lidx = rowl * 2 + lidx_base;
#pragma unroll
                for (int nt = 0; nt < 4; nt++) {
#pragma unroll
                    for (int j = 0; j < 2; j++) {
                        if (s[2 * nt + j] <= thr) {
                            int pos = atomicAdd(&cnt[lidx], 1);
                            if (pos < CAP)
                                cand[lidx * CAP + pos] =
                                    (uint16_t)(c0t + warp_n * 32 + nt * 8 + 2 * c4 + j);
                        }
                    }
                }
            }
#pragma unroll
            for (int mt = 0; mt < 2; mt++)
#pragma unroll
                for (int nt = 0; nt < 4; nt++)
#pragma unroll
                    for (int j = 0; j < 4; j++) acc[mt][nt][j] = 0;
        }
    }
    __syncthreads();   // publish all warps' candidate lists before rescore

    // ---- exact fp32 rescore (one warp per 8 rows) ----
    for (int j = 0; j < 8; j++) {
        const int rowl = wid * 8 + j;
        const int grow = r0 + rowl;
        float zreg[16];
#pragma unroll
        for (int p = 0; p < 16; p++) {
            int k = lane + 32 * p;
            zreg[p] = (k < DHALF) ? zr[(size_t)grow * DHALF + k]
                                  : zi[(size_t)grow * DHALF + k - DHALF];
        }
        float bv = 3.4e38f;
        int   bi = 0x7fffffff;

        int c0 = cnt[rowl * 2], c1 = cnt[rowl * 2 + 1];
        bool ovf = (c0 > CAP) || (c1 > CAP);
        int n0 = min(c0, CAP), n1 = min(c1, CAP);

        if (!ovf) {
            for (int tt = 0; tt < n0 + n1; tt++) {
                int code = (tt < n0) ? cand[(rowl * 2) * CAP + tt]
                                     : cand[(rowl * 2 + 1) * CAP + tt - n0];
                const float* wrow = &w[(size_t)code * KDIM];
                float dot = 0.f;
#pragma unroll
                for (int p = 0; p < 16; p++) dot = fmaf(zreg[p], wrow[lane + 32 * p], dot);
#pragma unroll
                for (int m = 16; m >= 1; m >>= 1) dot += __shfl_xor_sync(0xffffffffu, dot, m);
                float ex = fmaf(-2.f, dot, __ldg(&g_w2[code]));
                if (ex < bv || (ex == bv && code < bi)) { bv = ex; bi = code; }
            }
        } else {
            // guaranteed-correct fallback: exact scan over ALL codes (~never taken)
            for (int code = 0; code < VCODES; code++) {
                const float* wrow = &w[(size_t)code * KDIM];
                float dot = 0.f;
#pragma unroll
                for (int p = 0; p < 16; p++) dot = fmaf(zreg[p], wrow[lane + 32 * p], dot);
#pragma unroll
                for (int m = 16; m >= 1; m >>= 1) dot += __shfl_xor_sync(0xffffffffu, dot, m);
                float ex = fmaf(-2.f, dot, __ldg(&g_w2[code]));
                if (ex < bv) { bv = ex; bi = code; }   // strict <: first index wins
            }
        }
        if (lane == 0) g_idx[grow] = bi;
    }
}

// ---------------------------------------------------------------------------
// Gather z_q, outputs, per-row loss, histogram
// out layout: [z_q_real N*D][z_q_imag N*D][loss N][idx N][entropy 1]
// ---------------------------------------------------------------------------
__global__ void gather_kernel(const float* __restrict__ zr, const float* __restrict__ zi,
                              const float* __restrict__ w, float* __restrict__ out) {
    int row  = blockIdx.x * 8 + (threadIdx.x >> 5);
    int lane = threadIdx.x & 31;
    if (row >= N_ROWS) return;

    int ci = g_idx[row];
    const float* wrow = w + (size_t)ci * KDIM;
    float ss = 0.f;
#pragma unroll
    for (int p = 0; p < DHALF / 32; p++) {
        int d = lane + p * 32;
        float wv = wrow[d];
        float zv = zr[(size_t)row * DHALF + d];
        out[(size_t)row * DHALF + d] = wv;
        float df = wv - zv;
        ss = fmaf(df, df, ss);
    }
#pragma unroll
    for (int p = 0; p < DHALF / 32; p++) {
        int d = lane + p * 32;
        float wv = wrow[DHALF + d];
        float zv = zi[(size_t)row * DHALF + d];
        out[(size_t)N_ROWS * DHALF + (size_t)row * DHALF + d] = wv;
        float df = wv - zv;
        ss = fmaf(df, df, ss);
    }
#pragma unroll
    for (int m = 16; m >= 1; m >>= 1) ss += __shfl_xor_sync(0xffffffffu, ss, m);
    if (lane == 0) {
        size_t base = (size_t)2 * N_ROWS * DHALF;
        out[base + row] = ss * (1.25f / (float)KDIM);
        out[base + N_ROWS + row] = (float)ci;
        atomicAdd(&g_counts[ci], 1);
    }
}

__global__ void entropy_kernel(float* __restrict__ out) {
    __shared__ float red[1024];
    int t = threadIdx.x;
    float s = 0.f;
    for (int v = t; v < VCODES; v += 1024) {
        float p = (float)g_counts[v] * (1.f / (float)N_ROWS);
        s += p * logf(p + 1e-10f);
    }
    red[t] = s;
    __syncthreads();
    for (int m = 512; m >= 1; m >>= 1) {
        if (t < m) red[t] += red[t + m];
        __syncthreads();
    }
    if (t == 0) out[(size_t)2 * N_ROWS * DHALF + 2 * N_ROWS] = -red[0];
}

// ---------------------------------------------------------------------------
extern "C" void kernel_launch(void* const* d_in, const int* in_sizes, int n_in,
                              void* d_out, int out_size) {
    const float* zr = (const float*)d_in[0];
    const float* zi = (const float*)d_in[1];
    const float* w  = (const float*)d_in[2];
    float* out = (float*)d_out;

    cudaFuncSetAttribute(vq_mma_kernel,
                         cudaFuncAttributeMaxDynamicSharedMemorySize, SMEM_TOTAL);

    maxabs3_kernel<<<384, 256>>>(zr, zi, w);
    quant_z_kernel<<<(N_ROWS * KDIM / 4 + 255) / 256, 256>>>(zr, zi);
    quant_w2_kernel<<<VCODES / 8, 256>>>(w);
    vq_mma_kernel<<<N_ROWS / BR, NTHREADS, SMEM_TOTAL>>>(zr, zi, w);
    gather_kernel<<<N_ROWS / 8, 256>>>(zr, zi, w, out);
    entropy_kernel<<<1, 1024>>>(out);
}

// round 15
// speedup vs baseline: 4.5166x; 4.5166x over previous
#include <cuda_runtime.h>
#include <cstdint>
#include <math.h>

// Problem constants
#define N_ROWS 16384
#define DHALF  256
#define KDIM   512                     // s8 bytes per row = floats per row
#define VCODES 8192

// Tiling: full-K stages, A resident, 16 warps in 4x4, warp tile 32x32
#define BR 128
#define BC 128
#define N_TILES (VCODES / BC)          // 64 stages
#define NTHREADS 512

#define MARGIN 0.5f
#define CAP 48

// SMEM: rows padded to 528B (528 mod 128 = 16 -> conflict-free ldmatrix)
#define ROWB 528
#define A_STAGE (BR * ROWB)            // 67584
#define B_STAGE (BC * ROWB)            // 67584
#define OFF_A  0
#define OFF_B0 (A_STAGE)
#define OFF_B1 (A_STAGE + B_STAGE)
#define OFF_CAND (A_STAGE + 2 * B_STAGE)          // 202752: uint16[128][2][CAP]
#define OFF_CNT  (OFF_CAND + BR * 2 * CAP * 2)    // 227328: int[128][2]
#define OFF_RMIN (OFF_CNT + 1024)                 // 228352: int[128]
#define SMEM_TOTAL (OFF_RMIN + 512)               // 228864

// Scratch globals
__device__ float   g_w2[VCODES];
__device__ int     g_counts[VCODES];
__device__ int     g_idx[N_ROWS];
__device__ float   g_bmax[384];        // per-block maxima: [0..255]=z, [256..383]=w
__device__ float   g_maxz;
__device__ float   g_maxw;
__device__ int8_t  g_z8[(size_t)N_ROWS * KDIM];
__device__ int8_t  g_w8[(size_t)VCODES * KDIM];

// ---------------------------------------------------------------------------
__device__ __forceinline__ uint32_t smem_u32(const void* p) {
    uint32_t a;
    asm("{ .reg .u64 t; cvta.to.shared.u64 t, %1; cvt.u32.u64 %0, t; }" : "=r"(a) : "l"(p));
    return a;
}
#define CP_ASYNC16(dst, src) \
    asm volatile("cp.async.cg.shared.global [%0], [%1], 16;" :: "r"(dst), "l"(src) : "memory")
#define CP_ASYNC_COMMIT() asm volatile("cp.async.commit_group;" ::: "memory")
#define CP_ASYNC_WAIT0()  asm volatile("cp.async.wait_group 0;" ::: "memory")

#define LDSM_X4(r0, r1, r2, r3, addr) \
    asm volatile("ldmatrix.sync.aligned.m8n8.x4.shared.b16 {%0,%1,%2,%3}, [%4];" \
        : "=r"(r0), "=r"(r1), "=r"(r2), "=r"(r3) : "r"(addr))

#define MMA_S8(C, a0, a1, a2, a3, b0, b1) \
    asm volatile("mma.sync.aligned.m16n8k32.row.col.s32.s8.s8.s32 " \
        "{%0,%1,%2,%3}, {%4,%5,%6,%7}, {%8,%9}, {%0,%1,%2,%3};" \
        : "+r"((C)[0]), "+r"((C)[1]), "+r"((C)[2]), "+r"((C)[3]) \
        : "r"(a0), "r"(a1), "r"(a2), "r"(a3), "r"(b0), "r"(b1))

// ordered-int encoding of float: monotonic for signed-int comparison
__device__ __forceinline__ int enc_f(float f) {
    int i = __float_as_int(f);
    return (i >= 0) ? i : (i ^ 0x7FFFFFFF);
}
__device__ __forceinline__ float dec_f(int i) {
    return __int_as_float((i >= 0) ? i : (i ^ 0x7FFFFFFF));
}

// ---------------------------------------------------------------------------
// Pass 1 of max-abs: per-block maxima (no atomics). Also zeroes g_counts.
// Grid: 384 blocks x 256. seg 0: zr, seg 1: zi, seg 2: w.
// ---------------------------------------------------------------------------
__global__ void maxabs3_kernel(const float* __restrict__ zr, const float* __restrict__ zi,
                               const float* __restrict__ w) {
    __shared__ float sred[8];
    int seg = blockIdx.x >> 7;
    int b   = blockIdx.x & 127;
    const float* p = (seg == 0) ? zr : (seg == 1) ? zi : w;
    int n4 = (seg == 2) ? (VCODES * KDIM / 4) : (N_ROWS * DHALF / 4);
    int stride = 128 * blockDim.x;
    float m = 0.f;
    for (int i = b * blockDim.x + threadIdx.x; i < n4; i += stride) {
        float4 v = ((const float4*)p)[i];
        m = fmaxf(m, fmaxf(fmaxf(fabsf(v.x), fabsf(v.y)), fmaxf(fabsf(v.z), fabsf(v.w))));
    }
#pragma unroll
    for (int s = 16; s >= 1; s >>= 1) m = fmaxf(m, __shfl_xor_sync(0xffffffffu, m, s));
    if ((threadIdx.x & 31) == 0) sred[threadIdx.x >> 5] = m;
    __syncthreads();
    if (threadIdx.x == 0) {
        float bm = sred[0];
#pragma unroll
        for (int i = 1; i < 8; i++) bm = fmaxf(bm, sred[i]);
        g_bmax[blockIdx.x] = bm;
    }
    int gi = blockIdx.x * blockDim.x + threadIdx.x;
    if (gi < VCODES) g_counts[gi] = 0;
}

// block-reduce helper over g_bmax[base .. base+n)
__device__ __forceinline__ float reduce_bmax(float* sm, int base, int n) {
    int t = threadIdx.x;
    sm[t] = (t < n) ? g_bmax[base + t] : 0.f;
    __syncthreads();
    for (int s = 128; s >= 1; s >>= 1) {
        if (t < s) sm[t] = fmaxf(sm[t], sm[t + s]);
        __syncthreads();
    }
    float r = sm[0];
    __syncthreads();
    return r;
}

// ---------------------------------------------------------------------------
__global__ void quant_z_kernel(const float* __restrict__ zr, const float* __restrict__ zi) {
    __shared__ float sm[256];
    float mz = reduce_bmax(sm, 0, 256);
    if (blockIdx.x == 0 && threadIdx.x == 0) g_maxz = mz;
    float inv = 127.f / mz;
    int q = blockIdx.x * blockDim.x + threadIdx.x;           // float4 index
    if (q >= N_ROWS * KDIM / 4) return;
    int row = q >> 7, kq = (q & 127) * 4;
    float4 v = (kq < DHALF) ? *(const float4*)&zr[(size_t)row * DHALF + kq]
                            : *(const float4*)&zi[(size_t)row * DHALF + kq - DHALF];
    char4 c;
    c.x = (char)__float2int_rn(v.x * inv);
    c.y = (char)__float2int_rn(v.y * inv);
    c.z = (char)__float2int_rn(v.z * inv);
    c.w = (char)__float2int_rn(v.w * inv);
    *(char4*)&g_z8[(size_t)row * KDIM + kq] = c;
}

// fused: quantize w + compute w2 in one pass (one warp per code row)
__global__ void quant_w2_kernel(const float* __restrict__ w) {
    __shared__ float sm[256];
    float mw = reduce_bmax(sm, 256, 128);
    if (blockIdx.x == 0 && threadIdx.x == 0) g_maxw = mw;
    float inv = 127.f / mw;
    int row  = blockIdx.x * 8 + (threadIdx.x >> 5);
    int lane = threadIdx.x & 31;
    const float4* wr = (const float4*)(w + (size_t)row * KDIM);
    float ss = 0.f;
#pragma unroll
    for (int p = 0; p < 4; p++) {
        float4 v = wr[lane + p * 32];
        ss = fmaf(v.x, v.x, ss); ss = fmaf(v.y, v.y, ss);
        ss = fmaf(v.z, v.z, ss); ss = fmaf(v.w, v.w, ss);
        char4 c;
        c.x = (char)__float2int_rn(v.x * inv);
        c.y = (char)__float2int_rn(v.y * inv);
        c.z = (char)__float2int_rn(v.z * inv);
        c.w = (char)__float2int_rn(v.w * inv);
        *(char4*)&g_w8[(size_t)row * KDIM + (lane + p * 32) * 4] = c;
    }
#pragma unroll
    for (int m = 16; m >= 1; m >>= 1) ss += __shfl_xor_sync(0xffffffffu, ss, m);
    if (lane == 0) g_w2[row] = ss;
}

// ---------------------------------------------------------------------------
// Loaders: full 128-row x 512B tiles, 512 threads (8 chunks per thread)
// ---------------------------------------------------------------------------
__device__ __forceinline__ void load_A(uint32_t sa, int r0, int t) {
#pragma unroll
    for (int p = 0; p < 8; p++) {
        int e = t + p * NTHREADS;
        int row = e >> 5, g = e & 31;
        CP_ASYNC16(sa + (uint32_t)(row * ROWB + g * 16),
                   &g_z8[(size_t)(r0 + row) * KDIM + g * 16]);
    }
}
__device__ __forceinline__ void load_B(uint32_t sbb, int ct, int t) {
#pragma unroll
    for (int p = 0; p < 8; p++) {
        int e = t + p * NTHREADS;
        int row = e >> 5, g = e & 31;
        CP_ASYNC16(sbb + (uint32_t)(row * ROWB + g * 16),
                   &g_w8[(size_t)(ct * BC + row) * KDIM + g * 16]);
    }
}

// ---------------------------------------------------------------------------
// Fused: s8 IMMA prune -> candidate lists -> exact fp32 rescore
// 16 warps: warp_m = wid&3 (32 rows), warp_n = wid>>2 (32 cols). 4 warps/SMSP.
// Shared per-row running min (atomicMin on ordered-int) keeps thresholds tight.
// ---------------------------------------------------------------------------
__global__ __launch_bounds__(NTHREADS, 1)
void vq_mma_kernel(const float* __restrict__ zr, const float* __restrict__ zi,
                   const float* __restrict__ w) {
    extern __shared__ char smem[];
    const uint32_t sb = smem_u32(smem);
    const int t = threadIdx.x;
    const int wid = t >> 5, lane = t & 31;
    const int warp_m = wid & 3, warp_n = wid >> 2;
    const int q = lane >> 2, c4 = lane & 3;
    const int r0 = blockIdx.x * BR;

    const float s2 = -2.f * (g_maxz / 127.f) * (g_maxw / 127.f);

    uint16_t* cand = (uint16_t*)(smem + OFF_CAND);
    int*      cnt  = (int*)(smem + OFF_CNT);
    int*      rmin = (int*)(smem + OFF_RMIN);
    if (t < 256) cnt[t] = 0;                      // 256 counters [128][2]
    if (t < 128) rmin[t] = 0x7FFFFFFF;            // +inf encoding

    int acc[2][4][4];                             // 32 regs
#pragma unroll
    for (int mt = 0; mt < 2; mt++)
#pragma unroll
        for (int nt = 0; nt < 4; nt++)
#pragma unroll
            for (int j = 0; j < 4; j++) acc[mt][nt][j] = 0;

    load_A(sb + OFF_A, r0, t);
    load_B(sb + OFF_B0, 0, t);
    CP_ASYNC_COMMIT();

    const uint32_t a_row  = (lane & 7) + ((lane >> 3) & 1) * 8;
    const uint32_t a_koff = ((lane >> 4) & 1) * 16;
    const uint32_t b_row  = (lane & 7) + ((lane >> 4) & 1) * 8;
    const uint32_t b_koff = ((lane >> 3) & 1) * 16;

    const uint32_t a_base = sb + OFF_A + (warp_m * 32 + a_row) * ROWB + a_koff;
    const int lidx_base = warp_n >> 1;            // two warp_n share a list

    for (int ct = 0; ct < N_TILES; ct++) {
        CP_ASYNC_WAIT0();
        __syncthreads();
        if (ct + 1 < N_TILES) {
            load_B(sb + (((ct + 1) & 1) ? OFF_B1 : OFF_B0), ct + 1, t);
            CP_ASYNC_COMMIT();
        }

        {
            const uint32_t bbase = sb + ((ct & 1) ? OFF_B1 : OFF_B0)
                                 + (warp_n * 32 + b_row) * ROWB + b_koff;
#pragma unroll
            for (int kb = 0; kb < 16; kb++) {
                const uint32_t koff = kb * 32;
                uint32_t a[2][4];
#pragma unroll
                for (int mt = 0; mt < 2; mt++)
                    LDSM_X4(a[mt][0], a[mt][1], a[mt][2], a[mt][3],
                            a_base + mt * (16 * ROWB) + koff);
#pragma unroll
                for (int ntp = 0; ntp < 2; ntp++) {
                    uint32_t b0, b1, b2, b3;
                    LDSM_X4(b0, b1, b2, b3, bbase + ntp * (16 * ROWB) + koff);
#pragma unroll
                    for (int mt = 0; mt < 2; mt++) {
                        MMA_S8(acc[mt][2 * ntp],     a[mt][0], a[mt][1], a[mt][2], a[mt][3], b0, b1);
                        MMA_S8(acc[mt][2 * ntp + 1], a[mt][0], a[mt][1], a[mt][2], a[mt][3], b2, b3);
                    }
                }
            }
        }

        // ---- stage = full K: scores, shared running min, candidate append ----
        {
            const int c0t = ct * BC;
            float w2v[4][2];
#pragma unroll
            for (int nt = 0; nt < 4; nt++) {
                int c = c0t + warp_n * 32 + nt * 8 + 2 * c4;
                w2v[nt][0] = __ldg(&g_w2[c]);
                w2v[nt][1] = __ldg(&g_w2[c + 1]);
            }
#pragma unroll
            for (int rr = 0; rr < 4; rr++) {
                const int mt = rr >> 1, h = rr & 1;
                float s[8];
#pragma unroll
                for (int nt = 0; nt < 4; nt++) {
                    s[2 * nt]     = fmaf(s2, (float)acc[mt][nt][2 * h],     w2v[nt][0]);
                    s[2 * nt + 1] = fmaf(s2, (float)acc[mt][nt][2 * h + 1], w2v[nt][1]);
                }
                float m = s[0];
#pragma unroll
                for (int j = 1; j < 8; j++) m = fminf(m, s[j]);
                m = fminf(m, __shfl_xor_sync(0xffffffffu, m, 1));
                m = fminf(m, __shfl_xor_sync(0xffffffffu, m, 2));   // per-row min of warp's 32 codes
                const int rowl = warp_m * 32 + mt * 16 + h * 8 + q;

                // shared per-row running min: update + combine with own info.
                // Other warps' updates arrive with lag -> threshold only looser
                // -> still a superset. Tightest available info used immediately.
                int em = enc_f(m);
                int old = atomicAdd(&rmin[rowl], 0);     // read current
                old = atomicMin(&rmin[rowl], em);
                int cur = (em < old) ? em : old;
                const float thr = dec_f(cur) + MARGIN;

                const int lidx = rowl * 2 + lidx_base;
#pragma unroll
                for (int nt = 0; nt < 4; nt++) {
#pragma unroll
                    for (int j = 0; j < 2; j++) {
                        if (s[2 * nt + j] <= thr) {
                            int pos = atomicAdd(&cnt[lidx], 1);
                            if (pos < CAP)
                                cand[lidx * CAP + pos] =
                                    (uint16_t)(c0t + warp_n * 32 + nt * 8 + 2 * c4 + j);
                        }
                    }
                }
            }
#pragma unroll
            for (int mt = 0; mt < 2; mt++)
#pragma unroll
                for (int nt = 0; nt < 4; nt++)
#pragma unroll
                    for (int j = 0; j < 4; j++) acc[mt][nt][j] = 0;
        }
    }
    __syncthreads();   // publish all warps' candidate lists before rescore

    // ---- exact fp32 rescore (one warp per 8 rows) ----
    for (int j = 0; j < 8; j++) {
        const int rowl = wid * 8 + j;
        const int grow = r0 + rowl;
        float zreg[16];
#pragma unroll
        for (int p = 0; p < 16; p++) {
            int k = lane + 32 * p;
            zreg[p] = (k < DHALF) ? zr[(size_t)grow * DHALF + k]
                                  : zi[(size_t)grow * DHALF + k - DHALF];
        }
        float bv = 3.4e38f;
        int   bi = 0x7fffffff;

        int c0 = cnt[rowl * 2], c1 = cnt[rowl * 2 + 1];
        bool ovf = (c0 > CAP) || (c1 > CAP);
        int n0 = min(c0, CAP), n1 = min(c1, CAP);

        if (!ovf) {
            for (int tt = 0; tt < n0 + n1; tt++) {
                int code = (tt < n0) ? cand[(rowl * 2) * CAP + tt]
                                     : cand[(rowl * 2 + 1) * CAP + tt - n0];
                const float* wrow = &w[(size_t)code * KDIM];
                float dot = 0.f;
#pragma unroll
                for (int p = 0; p < 16; p++) dot = fmaf(zreg[p], wrow[lane + 32 * p], dot);
#pragma unroll
                for (int m = 16; m >= 1; m >>= 1) dot += __shfl_xor_sync(0xffffffffu, dot, m);
                float ex = fmaf(-2.f, dot, __ldg(&g_w2[code]));
                if (ex < bv || (ex == bv && code < bi)) { bv = ex; bi = code; }
            }
        } else {
            // guaranteed-correct fallback: exact scan over ALL codes (~never taken)
            for (int code = 0; code < VCODES; code++) {
                const float* wrow = &w[(size_t)code * KDIM];
                float dot = 0.f;
#pragma unroll
                for (int p = 0; p < 16; p++) dot = fmaf(zreg[p], wrow[lane + 32 * p], dot);
#pragma unroll
                for (int m = 16; m >= 1; m >>= 1) dot += __shfl_xor_sync(0xffffffffu, dot, m);
                float ex = fmaf(-2.f, dot, __ldg(&g_w2[code]));
                if (ex < bv) { bv = ex; bi = code; }   // strict <: first index wins
            }
        }
        if (lane == 0) g_idx[grow] = bi;
    }
}

// ---------------------------------------------------------------------------
// Gather z_q, outputs, per-row loss, histogram
// out layout: [z_q_real N*D][z_q_imag N*D][loss N][idx N][entropy 1]
// ---------------------------------------------------------------------------
__global__ void gather_kernel(const float* __restrict__ zr, const float* __restrict__ zi,
                              const float* __restrict__ w, float* __restrict__ out) {
    int row  = blockIdx.x * 8 + (threadIdx.x >> 5);
    int lane = threadIdx.x & 31;
    if (row >= N_ROWS) return;

    int ci = g_idx[row];
    const float* wrow = w + (size_t)ci * KDIM;
    float ss = 0.f;
#pragma unroll
    for (int p = 0; p < DHALF / 32; p++) {
        int d = lane + p * 32;
        float wv = wrow[d];
        float zv = zr[(size_t)row * DHALF + d];
        out[(size_t)row * DHALF + d] = wv;
        float df = wv - zv;
        ss = fmaf(df, df, ss);
    }
#pragma unroll
    for (int p = 0; p < DHALF / 32; p++) {
        int d = lane + p * 32;
        float wv = wrow[DHALF + d];
        float zv = zi[(size_t)row * DHALF + d];
        out[(size_t)N_ROWS * DHALF + (size_t)row * DHALF + d] = wv;
        float df = wv - zv;
        ss = fmaf(df, df, ss);
    }
#pragma unroll
    for (int m = 16; m >= 1; m >>= 1) ss += __shfl_xor_sync(0xffffffffu, ss, m);
    if (lane == 0) {
        size_t base = (size_t)2 * N_ROWS * DHALF;
        out[base + row] = ss * (1.25f / (float)KDIM);
        out[base + N_ROWS + row] = (float)ci;
        atomicAdd(&g_counts[ci], 1);
    }
}

__global__ void entropy_kernel(float* __restrict__ out) {
    __shared__ float red[1024];
    int t = threadIdx.x;
    float s = 0.f;
    for (int v = t; v < VCODES; v += 1024) {
        float p = (float)g_counts[v] * (1.f / (float)N_ROWS);
        s += p * logf(p + 1e-10f);
    }
    red[t] = s;
    __syncthreads();
    for (int m = 512; m >= 1; m >>= 1) {
        if (t < m) red[t] += red[t + m];
        __syncthreads();
    }
    if (t == 0) out[(size_t)2 * N_ROWS * DHALF + 2 * N_ROWS] = -red[0];
}

// ---------------------------------------------------------------------------
extern "C" void kernel_launch(void* const* d_in, const int* in_sizes, int n_in,
                              void* d_out, int out_size) {
    const float* zr = (const float*)d_in[0];
    const float* zi = (const float*)d_in[1];
    const float* w  = (const float*)d_in[2];
    float* out = (float*)d_out;

    cudaFuncSetAttribute(vq_mma_kernel,
                         cudaFuncAttributeMaxDynamicSharedMemorySize, SMEM_TOTAL);

    maxabs3_kernel<<<384, 256>>>(zr, zi, w);
    quant_z_kernel<<<(N_ROWS * KDIM / 4 + 255) / 256, 256>>>(zr, zi);
    quant_w2_kernel<<<VCODES / 8, 256>>>(w);
    vq_mma_kernel<<<N_ROWS / BR, NTHREADS, SMEM_TOTAL>>>(zr, zi, w);
    gather_kernel<<<N_ROWS / 8, 256>>>(zr, zi, w, out);
    entropy_kernel<<<1, 1024>>>(out);
}